// round 2
// baseline (speedup 1.0000x reference)
#include <cuda_runtime.h>
#include <math.h>

// Problem constants
#define Bv 2
#define Sv 1024
#define Dv 768
#define Hv 12
#define Lv 12
#define Vv 50257
#define DHv 64
#define HIDv 9216
#define Mv (Bv*Sv)          // 2048 token rows

// ------------------- scratch (device globals; no runtime alloc) -------------------
__device__ float g_x  [Mv*Dv];        // running residual stream
__device__ float g_n1 [Mv*Dv];        // ln1 output
__device__ float g_qkv[Mv*3*Dv];      // qkv projection
__device__ float g_val[Mv*Dv];        // attention output (pre-proj)
__device__ float g_att[Mv*Dv];        // after Wo + residual
__device__ float g_n2 [Mv*Dv];        // ln2 output
__device__ float g_ffn[Mv*HIDv];      // ffn hidden

// ------------------------------- embedding -------------------------------
__global__ void embed_kernel(const int* __restrict__ vocab,
                             const int* __restrict__ pos,
                             const float* __restrict__ vW,
                             const float* __restrict__ pW) {
    int row = blockIdx.x;                    // 0..2047
    int v = vocab[row];
    int p = pos[row];
    const float* vr = vW + (long)v * Dv;
    const float* pr = pW + (long)p * Dv;
    float* o = g_x + (long)row * Dv;
    for (int d = threadIdx.x; d < Dv; d += blockDim.x)
        o[d] = vr[d] + pr[d];
}

// ------------------------------- layernorm -------------------------------
__global__ void __launch_bounds__(256) ln_kernel(const float* __restrict__ in,
                                                 const float* __restrict__ s,
                                                 const float* __restrict__ b,
                                                 float* __restrict__ out) {
    int row = blockIdx.x;
    const float* x = in + (long)row * Dv;
    __shared__ float red[256];
    int tid = threadIdx.x;

    float sum = 0.f;
    for (int d = tid; d < Dv; d += 256) sum += x[d];
    red[tid] = sum; __syncthreads();
    #pragma unroll
    for (int o = 128; o > 0; o >>= 1) {
        if (tid < o) red[tid] += red[tid + o];
        __syncthreads();
    }
    float mean = red[0] * (1.0f / Dv);
    __syncthreads();

    float vs = 0.f;
    for (int d = tid; d < Dv; d += 256) { float t = x[d] - mean; vs += t * t; }
    red[tid] = vs; __syncthreads();
    #pragma unroll
    for (int o = 128; o > 0; o >>= 1) {
        if (tid < o) red[tid] += red[tid + o];
        __syncthreads();
    }
    float rstd = rsqrtf(red[0] * (1.0f / Dv) + 1e-5f);

    float* orow = out + (long)row * Dv;
    for (int d = tid; d < Dv; d += 256)
        orow[d] = (x[d] - mean) * rstd * s[d] + b[d];
}

// ------------------------------- SGEMM -------------------------------
// C[M,N] = A[M,K] @ B[K,N]  (+bias[n]) (leaky-relu) (+res[m,n])
// BM=BN=128, BK=8, 256 threads, 8x8 per thread. M must be multiple of 128.
template<int BIAS, int RELU, int RES>
__global__ void __launch_bounds__(256) gemm_kernel(
    const float* __restrict__ A, const float* __restrict__ Bm,
    const float* __restrict__ bias, const float* __restrict__ res,
    float* __restrict__ C, int M, int N, int K)
{
    const int BM = 128, BN = 128, BK = 8, TM = 8, TN = 8;
    __shared__ float As[BK][BM];
    __shared__ float Bs[BK][BN + 4];

    int tid = threadIdx.x;
    int n0 = blockIdx.x * BN;
    int m0 = blockIdx.y * BM;

    // A-tile load mapping: each thread loads float4 of A (row a_row, cols a_col..+3)
    int a_row = tid >> 1;
    int a_col = (tid & 1) * 4;
    // B-tile load mapping: row b_row, cols b_col..+3
    int b_row = tid >> 5;
    int b_col = (tid & 31) * 4;

    int tx = tid & 15;       // 0..15 -> n
    int ty = tid >> 4;       // 0..15 -> m

    float acc[TM][TN];
    #pragma unroll
    for (int i = 0; i < TM; i++)
        #pragma unroll
        for (int j = 0; j < TN; j++) acc[i][j] = 0.f;

    for (int k0 = 0; k0 < K; k0 += BK) {
        // load A (K divisible by 8; aligned -> float4 ok)
        const float4 a4 = *(const float4*)(A + (long)(m0 + a_row) * K + k0 + a_col);
        As[a_col + 0][a_row] = a4.x;
        As[a_col + 1][a_row] = a4.y;
        As[a_col + 2][a_row] = a4.z;
        As[a_col + 3][a_row] = a4.w;
        // load B (N may be ragged; scalar guarded loads)
        const float* Bp = Bm + (long)(k0 + b_row) * N + n0 + b_col;
        #pragma unroll
        for (int i = 0; i < 4; i++)
            Bs[b_row][b_col + i] = (n0 + b_col + i < N) ? Bp[i] : 0.f;
        __syncthreads();

        #pragma unroll
        for (int kk = 0; kk < BK; kk++) {
            float af[TM], bf[TN];
            #pragma unroll
            for (int i = 0; i < TM; i++) af[i] = As[kk][ty * TM + i];
            #pragma unroll
            for (int j = 0; j < TN; j++) bf[j] = Bs[kk][tx * TN + j];
            #pragma unroll
            for (int i = 0; i < TM; i++)
                #pragma unroll
                for (int j = 0; j < TN; j++)
                    acc[i][j] = fmaf(af[i], bf[j], acc[i][j]);
        }
        __syncthreads();
    }

    #pragma unroll
    for (int i = 0; i < TM; i++) {
        int m = m0 + ty * TM + i;
        #pragma unroll
        for (int j = 0; j < TN; j++) {
            int n = n0 + tx * TN + j;
            if (n < N) {
                float v = acc[i][j];
                if (BIAS) v += bias[n];
                if (RELU) v = (v > 0.f) ? v : 0.01f * v;
                if (RES)  v += res[(long)m * N + n];
                C[(long)m * N + n] = v;
            }
        }
    }
}

// ------------------------------- fused attention -------------------------------
// One thread per query row; 128 queries per block; keys streamed in 64-key
// smem chunks with online softmax. Masked logits == -1e5 (exp underflows to 0,
// matching the reference's multiplicative-mask trick exactly).
__global__ void __launch_bounds__(128) attn_kernel() {
    int bh = blockIdx.x;           // b*H + h
    int b  = bh / Hv;
    int h  = bh % Hv;
    int qt = blockIdx.y;           // query tile (128 queries)
    int tid = threadIdx.x;
    int qi = qt * 128 + tid;

    const float* qrow = g_qkv + (long)(b * Sv + qi) * (3 * Dv) + h * 3 * DHv;
    float q[DHv];
    #pragma unroll
    for (int d = 0; d < DHv; d++) q[d] = qrow[d];

    float o[DHv];
    #pragma unroll
    for (int d = 0; d < DHv; d++) o[d] = 0.f;
    float mx = -1e30f, l = 0.f;

    __shared__ float Ks[64][DHv];
    __shared__ float Vs[64][DHv];

    int kend = qt * 128 + 128;     // max key (exclusive) needed by this block

    for (int ks0 = 0; ks0 < kend; ks0 += 64) {
        // cooperative load of 64 keys + values (float4 per thread iter)
        for (int idx = tid; idx < 64 * 16; idx += 128) {
            int j  = idx >> 4;             // key within chunk
            int dc = (idx & 15) * 4;       // dim offset
            const float* kr = g_qkv + (long)(b * Sv + ks0 + j) * (3 * Dv)
                              + h * 3 * DHv + DHv + dc;
            *(float4*)&Ks[j][dc] = *(const float4*)kr;
            *(float4*)&Vs[j][dc] = *(const float4*)(kr + DHv);
        }
        __syncthreads();

        #pragma unroll 1
        for (int sub = 0; sub < 64; sub += 16) {
            float s[16];
            #pragma unroll
            for (int jj = 0; jj < 16; jj++) {
                float acc = 0.f;
                #pragma unroll
                for (int d = 0; d < DHv; d++)
                    acc = fmaf(q[d], Ks[sub + jj][d], acc);
                int kj = ks0 + sub + jj;
                s[jj] = (kj <= qi) ? acc * 0.125f : -1e5f;
            }
            float cm = s[0];
            #pragma unroll
            for (int jj = 1; jj < 16; jj++) cm = fmaxf(cm, s[jj]);
            float mnew = fmaxf(mx, cm);
            float scale = __expf(mx - mnew);
            l *= scale;
            #pragma unroll
            for (int d = 0; d < DHv; d++) o[d] *= scale;
            #pragma unroll
            for (int jj = 0; jj < 16; jj++) {
                float p = __expf(s[jj] - mnew);
                l += p;
                #pragma unroll
                for (int d = 0; d < DHv; d++)
                    o[d] = fmaf(p, Vs[sub + jj][d], o[d]);
            }
            mx = mnew;
        }
        __syncthreads();
    }

    float inv = 1.0f / l;
    float* outp = g_val + (long)(b * Sv + qi) * Dv + h * DHv;
    #pragma unroll
    for (int d = 0; d < DHv; d++) outp[d] = o[d] * inv;
}

// ------------------------------- driver -------------------------------
extern "C" void kernel_launch(void* const* d_in, const int* in_sizes, int n_in,
                              void* d_out, int out_size) {
    (void)in_sizes; (void)n_in; (void)out_size;
    const int*   vocab = (const int*)  d_in[0];
    const int*   pos   = (const int*)  d_in[1];
    const float* vW    = (const float*)d_in[2];
    const float* pW    = (const float*)d_in[3];
    const float* ln1_s = (const float*)d_in[4];
    const float* ln1_b = (const float*)d_in[5];
    const float* Wqkv  = (const float*)d_in[6];
    const float* bqkv  = (const float*)d_in[7];
    const float* Wo    = (const float*)d_in[8];
    const float* bo    = (const float*)d_in[9];
    const float* ln2_s = (const float*)d_in[10];
    const float* ln2_b = (const float*)d_in[11];
    const float* W1    = (const float*)d_in[12];
    const float* b1    = (const float*)d_in[13];
    const float* W2    = (const float*)d_in[14];
    const float* b2    = (const float*)d_in[15];
    const float* outW  = (const float*)d_in[16];
    float* out = (float*)d_out;

    // resolve device-global scratch addresses (host-side lookups; capture-safe)
    float *p_x, *p_n1, *p_qkv, *p_val, *p_att, *p_n2, *p_ffn;
    cudaGetSymbolAddress((void**)&p_x,   g_x);
    cudaGetSymbolAddress((void**)&p_n1,  g_n1);
    cudaGetSymbolAddress((void**)&p_qkv, g_qkv);
    cudaGetSymbolAddress((void**)&p_val, g_val);
    cudaGetSymbolAddress((void**)&p_att, g_att);
    cudaGetSymbolAddress((void**)&p_n2,  g_n2);
    cudaGetSymbolAddress((void**)&p_ffn, g_ffn);

    dim3 gemm_blk(256);

    // embedding
    embed_kernel<<<Mv, 256>>>(vocab, pos, vW, pW);

    for (int l = 0; l < Lv; l++) {
        const float* l1s = ln1_s + (long)l * Dv;
        const float* l1b = ln1_b + (long)l * Dv;
        const float* wq  = Wqkv  + (long)l * Dv * 3 * Dv;
        const float* bq  = bqkv  + (long)l * 3 * Dv;
        const float* wo  = Wo    + (long)l * Dv * Dv;
        const float* bo_ = bo    + (long)l * Dv;
        const float* l2s = ln2_s + (long)l * Dv;
        const float* l2b = ln2_b + (long)l * Dv;
        const float* w1  = W1    + (long)l * Dv * HIDv;
        const float* bb1 = b1    + (long)l * HIDv;
        const float* w2  = W2    + (long)l * HIDv * Dv;
        const float* bb2 = b2    + (long)l * Dv;

        // ln1
        ln_kernel<<<Mv, 256>>>(p_x, l1s, l1b, p_n1);
        // qkv = n1 @ Wqkv + bqkv        [2048, 2304]
        gemm_kernel<1,0,0><<<dim3((3*Dv+127)/128, Mv/128), gemm_blk>>>(
            p_n1, wq, bq, nullptr, p_qkv, Mv, 3*Dv, Dv);
        // attention -> g_val
        attn_kernel<<<dim3(Bv*Hv, Sv/128), 128>>>();
        // att = val @ Wo + bo + x       [2048, 768]
        gemm_kernel<1,0,1><<<dim3(Dv/128, Mv/128), gemm_blk>>>(
            p_val, wo, bo_, p_x, p_att, Mv, Dv, Dv);
        // ln2
        ln_kernel<<<Mv, 256>>>(p_att, l2s, l2b, p_n2);
        // ffn hidden = leaky_relu(n2 @ W1 + b1)   [2048, 9216]
        gemm_kernel<1,1,0><<<dim3(HIDv/128, Mv/128), gemm_blk>>>(
            p_n2, w1, bb1, nullptr, p_ffn, Mv, HIDv, Dv);
        // x = ffn @ W2 + b2 + n2        [2048, 768]   (residual is n2!)
        gemm_kernel<1,0,1><<<dim3(Dv/128, Mv/128), gemm_blk>>>(
            p_ffn, w2, bb2, p_n2, p_x, Mv, Dv, HIDv);
    }

    // logits = x @ out_W               [2048, 50257]
    gemm_kernel<0,0,0><<<dim3((Vv+127)/128, Mv/128), gemm_blk>>>(
        p_x, outW, nullptr, nullptr, out, Mv, Vv, Dv);
}

// round 4
// speedup vs baseline: 2.7346x; 2.7346x over previous
#include <cuda_runtime.h>
#include <cuda_bf16.h>
#include <cstdint>
#include <math.h>

#define Bv 2
#define Sv 1024
#define Dv 768
#define Hv 12
#define Lv 12
#define Vv 50257
#define DHv 64
#define HIDv 9216
#define Mv (Bv*Sv)

// ---------------- activation scratch ----------------
__device__ float g_x  [Mv*Dv];
__device__ float g_n1 [Mv*Dv];
__device__ float g_qkv[Mv*3*Dv];
__device__ float g_att[Mv*Dv];
__device__ float g_n2 [Mv*Dv];
__device__ float g_part[3L*Mv*Dv];
__device__ __nv_bfloat16 g_n1h[Mv*Dv],  g_n1l[Mv*Dv];
__device__ __nv_bfloat16 g_n2h[Mv*Dv],  g_n2l[Mv*Dv];
__device__ __nv_bfloat16 g_valh[Mv*Dv], g_vall[Mv*Dv];
__device__ __nv_bfloat16 g_xh[Mv*Dv],   g_xl[Mv*Dv];
__device__ __nv_bfloat16 g_ffnh[(size_t)Mv*HIDv], g_ffnl[(size_t)Mv*HIDv];
// transposed bf16 hi/lo weight planes ([N,K], K contiguous)
__device__ __nv_bfloat16 g_qkvT_h[(size_t)Lv*3*Dv*Dv], g_qkvT_l[(size_t)Lv*3*Dv*Dv];
__device__ __nv_bfloat16 g_woT_h [(size_t)Lv*Dv*Dv],   g_woT_l [(size_t)Lv*Dv*Dv];
__device__ __nv_bfloat16 g_w1T_h [(size_t)Lv*HIDv*Dv], g_w1T_l [(size_t)Lv*HIDv*Dv];
__device__ __nv_bfloat16 g_w2T_h [(size_t)Lv*Dv*HIDv], g_w2T_l [(size_t)Lv*Dv*HIDv];
__device__ __nv_bfloat16 g_outT_h[(size_t)Vv*Dv],      g_outT_l[(size_t)Vv*Dv];

// ---------------- PTX helpers (sm_80-class, valid on base sm_103) ----------------
__device__ __forceinline__ uint32_t smem_u32(const void* p) {
    uint32_t a;
    asm("{ .reg .u64 t; cvta.to.shared.u64 t, %1; cvt.u32.u64 %0, t; }" : "=r"(a) : "l"(p));
    return a;
}
__device__ __forceinline__ void cpa16(uint32_t dst, const void* src, bool valid) {
    int sz = valid ? 16 : 0;
    asm volatile("cp.async.cg.shared.global [%0], [%1], 16, %2;"
                 :: "r"(dst), "l"(src), "r"(sz) : "memory");
}
#define CP_COMMIT()  asm volatile("cp.async.commit_group;" ::: "memory")
#define CP_WAIT(n)   asm volatile("cp.async.wait_group %0;" :: "n"(n) : "memory")

__device__ __forceinline__ void ldsm4(uint32_t* r, uint32_t a) {
    asm volatile("ldmatrix.sync.aligned.m8n8.x4.shared.b16 {%0,%1,%2,%3}, [%4];"
        : "=r"(r[0]), "=r"(r[1]), "=r"(r[2]), "=r"(r[3]) : "r"(a));
}
__device__ __forceinline__ void ldsm2(uint32_t* r, uint32_t a) {
    asm volatile("ldmatrix.sync.aligned.m8n8.x2.shared.b16 {%0,%1}, [%2];"
        : "=r"(r[0]), "=r"(r[1]) : "r"(a));
}
__device__ __forceinline__ void mma16816(float* d, const uint32_t* a, const uint32_t* b) {
    asm volatile("mma.sync.aligned.m16n8k16.row.col.f32.bf16.bf16.f32 "
        "{%0,%1,%2,%3}, {%4,%5,%6,%7}, {%8,%9}, {%0,%1,%2,%3};"
        : "+f"(d[0]), "+f"(d[1]), "+f"(d[2]), "+f"(d[3])
        : "r"(a[0]), "r"(a[1]), "r"(a[2]), "r"(a[3]), "r"(b[0]), "r"(b[1]));
}

// ---------------- bf16x3 tensor-core GEMM ----------------
// C[M,N] = A[M,K] @ B^T (B stored [N,K]); A,B given as bf16 hi/lo planes.
// EPI: 0=+bias->f32  1=+bias+res->f32  2=+bias,lrelu->bf16 hi/lo  4=plain->f32  5=splitK partial->f32
// smem: 2 stages x (Ah,Al,Bh,Bl) tiles of 128 rows x 32 halves, pitch 80B.
#define STG   40960
#define PITCH 80
#define GSMEM (2*STG)
template<int EPI>
__global__ void __launch_bounds__(256, 1) mma_gemm(
    const __nv_bfloat16* __restrict__ Ah, const __nv_bfloat16* __restrict__ Al,
    const __nv_bfloat16* __restrict__ Bh, const __nv_bfloat16* __restrict__ Bl,
    const float* __restrict__ bias, const float* __restrict__ res,
    float* __restrict__ C, __nv_bfloat16* __restrict__ Oh, __nv_bfloat16* __restrict__ Ol,
    int N, int K, int ksplit)
{
    extern __shared__ char sm[];
    uint32_t sb = smem_u32(sm);
    int tid = threadIdx.x, wid = tid >> 5, lane = tid & 31;
    int m0 = blockIdx.y * 128, n0 = blockIdx.x * 128;
    int Kper = K / ksplit, kbase = blockIdx.z * Kper, niter = Kper >> 5;

    float acc[4][4][4];
    #pragma unroll
    for (int i = 0; i < 4; i++)
        #pragma unroll
        for (int j = 0; j < 4; j++)
            #pragma unroll
            for (int e = 0; e < 4; e++) acc[i][j][e] = 0.f;

    // stage loader: 512 (row,quarter) pairs x 4 planes
    auto stage_load = [&](int s, int k0) {
        uint32_t base = sb + s * STG;
        #pragma unroll
        for (int i = tid; i < 512; i += 256) {
            int r = i >> 2, q = i & 3;
            uint32_t so = base + r * PITCH + q * 16;
            size_t ao = (size_t)(m0 + r) * K + k0 + q * 8;
            cpa16(so,         Ah + ao, true);
            cpa16(so + 10240, Al + ao, true);
            bool v = (n0 + r) < N;
            int rr = v ? (n0 + r) : (N - 1);
            size_t bo = (size_t)rr * K + k0 + q * 8;
            cpa16(so + 20480, Bh + bo, v);
            cpa16(so + 30720, Bl + bo, v);
        }
    };

    stage_load(0, kbase);
    CP_COMMIT();

    int wm = (wid & 1) * 64, wn = (wid >> 1) * 32;
    int cur = 0;
    for (int it = 0; it < niter; it++) {
        if (it + 1 < niter) {
            stage_load(cur ^ 1, kbase + (it + 1) * 32);
            CP_COMMIT();
            CP_WAIT(1);
        } else {
            CP_WAIT(0);
        }
        __syncthreads();

        uint32_t base = sb + cur * STG;
        #pragma unroll
        for (int ks = 0; ks < 2; ks++) {
            uint32_t ah[4][4], al[4][4], bh[4][2], bl[4][2];
            int arow = wm + (lane & 15);
            uint32_t akb = ks * 32 + ((lane >> 4) << 4);
            #pragma unroll
            for (int i = 0; i < 4; i++) {
                uint32_t ao = base + (uint32_t)(arow + i * 16) * PITCH + akb;
                ldsm4(ah[i], ao);
                ldsm4(al[i], ao + 10240);
            }
            int brow = wn + (lane & 7);
            uint32_t bkb = ks * 32 + (((lane >> 3) & 1) << 4);
            #pragma unroll
            for (int j = 0; j < 4; j++) {
                uint32_t bo = base + 20480 + (uint32_t)(brow + j * 8) * PITCH + bkb;
                ldsm2(bh[j], bo);
                ldsm2(bl[j], bo + 10240);
            }
            #pragma unroll
            for (int i = 0; i < 4; i++)
                #pragma unroll
                for (int j = 0; j < 4; j++) {
                    mma16816(acc[i][j], ah[i], bh[j]);
                    mma16816(acc[i][j], ah[i], bl[j]);
                    mma16816(acc[i][j], al[i], bh[j]);
                }
        }
        __syncthreads();
        cur ^= 1;
    }

    // epilogue
    #pragma unroll
    for (int i = 0; i < 4; i++) {
        int r0 = m0 + wm + i * 16 + (lane >> 2);
        #pragma unroll
        for (int j = 0; j < 4; j++) {
            int c0 = n0 + wn + j * 8 + 2 * (lane & 3);
            #pragma unroll
            for (int e = 0; e < 4; e++) {
                int r = r0 + (e >> 1) * 8;
                int c = c0 + (e & 1);
                if (c < N) {
                    float v = acc[i][j][e];
                    if (EPI == 0 || EPI == 1 || EPI == 2) v += bias[c];
                    if (EPI == 1) v += res[(size_t)r * N + c];
                    if (EPI == 2) {
                        v = v > 0.f ? v : 0.01f * v;
                        __nv_bfloat16 h = __float2bfloat16(v);
                        Oh[(size_t)r * N + c] = h;
                        Ol[(size_t)r * N + c] = __float2bfloat16(v - __bfloat162float(h));
                    } else if (EPI == 5) {
                        C[(size_t)blockIdx.z * Mv * N + (size_t)r * N + c] = v;
                    } else {
                        C[(size_t)r * N + c] = v;
                    }
                }
            }
        }
    }
}

// ---------------- weight transpose + bf16 hi/lo split ----------------
__global__ void wconv(const float* __restrict__ W, __nv_bfloat16* __restrict__ Th,
                      __nv_bfloat16* __restrict__ Tl, int K, int N) {
    __shared__ float t[32][33];
    size_t zo = (size_t)blockIdx.z * K * N;
    const float* Wp = W + zo;
    __nv_bfloat16* Thp = Th + zo;
    __nv_bfloat16* Tlp = Tl + zo;
    int k0 = blockIdx.y * 32, n0 = blockIdx.x * 32;
    for (int i = threadIdx.y; i < 32; i += 8) {
        int k = k0 + i, n = n0 + threadIdx.x;
        t[i][threadIdx.x] = (k < K && n < N) ? Wp[(size_t)k * N + n] : 0.f;
    }
    __syncthreads();
    for (int i = threadIdx.y; i < 32; i += 8) {
        int n = n0 + i, k = k0 + threadIdx.x;
        if (n < N && k < K) {
            float v = t[threadIdx.x][i];
            __nv_bfloat16 h = __float2bfloat16(v);
            Thp[(size_t)n * K + k] = h;
            Tlp[(size_t)n * K + k] = __float2bfloat16(v - __bfloat162float(h));
        }
    }
}

// ---------------- split-K reduce for W2 ----------------
__global__ void reduce_w2(const float* __restrict__ part, const float* __restrict__ b2,
                          const float* __restrict__ n2, float* __restrict__ x,
                          __nv_bfloat16* __restrict__ xh, __nv_bfloat16* __restrict__ xl) {
    int i = blockIdx.x * 256 + threadIdx.x;
    float v = part[i] + part[i + (size_t)Mv * Dv] + part[i + 2ul * Mv * Dv]
            + b2[i % Dv] + n2[i];
    x[i] = v;
    __nv_bfloat16 h = __float2bfloat16(v);
    xh[i] = h; xl[i] = __float2bfloat16(v - __bfloat162float(h));
}

// ---------------- embedding ----------------
__global__ void embed_kernel(const int* __restrict__ vocab, const int* __restrict__ pos,
                             const float* __restrict__ vW, const float* __restrict__ pW) {
    int row = blockIdx.x;
    const float* vr = vW + (long)vocab[row] * Dv;
    const float* pr = pW + (long)pos[row] * Dv;
    float* o = g_x + (long)row * Dv;
    for (int d = threadIdx.x; d < Dv; d += blockDim.x) o[d] = vr[d] + pr[d];
}

// ---------------- layernorm (fp32 + hi/lo planes) ----------------
__global__ void __launch_bounds__(256) ln_kernel(const float* __restrict__ in,
        const float* __restrict__ s, const float* __restrict__ b,
        float* __restrict__ out, __nv_bfloat16* __restrict__ oh, __nv_bfloat16* __restrict__ ol) {
    int row = blockIdx.x;
    const float* x = in + (long)row * Dv;
    __shared__ float red[256];
    int tid = threadIdx.x;
    float sum = 0.f;
    for (int d = tid; d < Dv; d += 256) sum += x[d];
    red[tid] = sum; __syncthreads();
    #pragma unroll
    for (int o = 128; o > 0; o >>= 1) { if (tid < o) red[tid] += red[tid + o]; __syncthreads(); }
    float mean = red[0] * (1.0f / Dv);
    __syncthreads();
    float vs = 0.f;
    for (int d = tid; d < Dv; d += 256) { float t = x[d] - mean; vs += t * t; }
    red[tid] = vs; __syncthreads();
    #pragma unroll
    for (int o = 128; o > 0; o >>= 1) { if (tid < o) red[tid] += red[tid + o]; __syncthreads(); }
    float rstd = rsqrtf(red[0] * (1.0f / Dv) + 1e-5f);
    long base = (long)row * Dv;
    for (int d = tid; d < Dv; d += 256) {
        float v = (x[d] - mean) * rstd * s[d] + b[d];
        out[base + d] = v;
        __nv_bfloat16 h = __float2bfloat16(v);
        oh[base + d] = h;
        ol[base + d] = __float2bfloat16(v - __bfloat162float(h));
    }
}

// ---------------- fused attention (epilogue -> bf16 hi/lo) ----------------
__global__ void __launch_bounds__(128) attn_kernel() {
    int bh = blockIdx.x;
    int b = bh / Hv, h = bh % Hv;
    int qt = blockIdx.y;
    int tid = threadIdx.x;
    int qi = qt * 128 + tid;

    const float* qrow = g_qkv + (long)(b * Sv + qi) * (3 * Dv) + h * 3 * DHv;
    float q[DHv];
    #pragma unroll
    for (int d = 0; d < DHv; d++) q[d] = qrow[d];
    float o[DHv];
    #pragma unroll
    for (int d = 0; d < DHv; d++) o[d] = 0.f;
    float mx = -1e30f, l = 0.f;

    __shared__ float Ks[64][DHv];
    __shared__ float Vs[64][DHv];
    int kend = qt * 128 + 128;

    for (int ks0 = 0; ks0 < kend; ks0 += 64) {
        for (int idx = tid; idx < 64 * 16; idx += 128) {
            int j = idx >> 4, dc = (idx & 15) * 4;
            const float* kr = g_qkv + (long)(b * Sv + ks0 + j) * (3 * Dv) + h * 3 * DHv + DHv + dc;
            *(float4*)&Ks[j][dc] = *(const float4*)kr;
            *(float4*)&Vs[j][dc] = *(const float4*)(kr + DHv);
        }
        __syncthreads();
        #pragma unroll 1
        for (int sub = 0; sub < 64; sub += 16) {
            float s[16];
            #pragma unroll
            for (int jj = 0; jj < 16; jj++) {
                float acc = 0.f;
                #pragma unroll
                for (int d = 0; d < DHv; d++) acc = fmaf(q[d], Ks[sub + jj][d], acc);
                int kj = ks0 + sub + jj;
                s[jj] = (kj <= qi) ? acc * 0.125f : -1e5f;
            }
            float cm = s[0];
            #pragma unroll
            for (int jj = 1; jj < 16; jj++) cm = fmaxf(cm, s[jj]);
            float mnew = fmaxf(mx, cm);
            float scale = __expf(mx - mnew);
            l *= scale;
            #pragma unroll
            for (int d = 0; d < DHv; d++) o[d] *= scale;
            #pragma unroll
            for (int jj = 0; jj < 16; jj++) {
                float p = __expf(s[jj] - mnew);
                l += p;
                #pragma unroll
                for (int d = 0; d < DHv; d++) o[d] = fmaf(p, Vs[sub + jj][d], o[d]);
            }
            mx = mnew;
        }
        __syncthreads();
    }
    float inv = 1.0f / l;
    long base = (long)(b * Sv + qi) * Dv + h * DHv;
    #pragma unroll
    for (int d = 0; d < DHv; d++) {
        float vv = o[d] * inv;
        __nv_bfloat16 hh = __float2bfloat16(vv);
        g_valh[base + d] = hh;
        g_vall[base + d] = __float2bfloat16(vv - __bfloat162float(hh));
    }
}

// ---------------- driver ----------------
extern "C" void kernel_launch(void* const* d_in, const int* in_sizes, int n_in,
                              void* d_out, int out_size) {
    (void)in_sizes; (void)n_in; (void)out_size;
    const int*   vocab = (const int*)  d_in[0];
    const int*   pos   = (const int*)  d_in[1];
    const float* vW    = (const float*)d_in[2];
    const float* pW    = (const float*)d_in[3];
    const float* ln1_s = (const float*)d_in[4];
    const float* ln1_b = (const float*)d_in[5];
    const float* Wqkv  = (const float*)d_in[6];
    const float* bqkv  = (const float*)d_in[7];
    const float* Wo    = (const float*)d_in[8];
    const float* bo    = (const float*)d_in[9];
    const float* ln2_s = (const float*)d_in[10];
    const float* ln2_b = (const float*)d_in[11];
    const float* W1    = (const float*)d_in[12];
    const float* b1    = (const float*)d_in[13];
    const float* W2    = (const float*)d_in[14];
    const float* b2    = (const float*)d_in[15];
    const float* outW  = (const float*)d_in[16];
    float* out = (float*)d_out;

    static bool attr_done = false;
    if (!attr_done) {
        cudaFuncSetAttribute(mma_gemm<0>, cudaFuncAttributeMaxDynamicSharedMemorySize, GSMEM);
        cudaFuncSetAttribute(mma_gemm<1>, cudaFuncAttributeMaxDynamicSharedMemorySize, GSMEM);
        cudaFuncSetAttribute(mma_gemm<2>, cudaFuncAttributeMaxDynamicSharedMemorySize, GSMEM);
        cudaFuncSetAttribute(mma_gemm<4>, cudaFuncAttributeMaxDynamicSharedMemorySize, GSMEM);
        cudaFuncSetAttribute(mma_gemm<5>, cudaFuncAttributeMaxDynamicSharedMemorySize, GSMEM);
        attr_done = true;
    }

    float *p_x, *p_n1, *p_qkv, *p_att, *p_n2, *p_part;
    __nv_bfloat16 *p_n1h, *p_n1l, *p_n2h, *p_n2l, *p_valh, *p_vall, *p_xh, *p_xl, *p_ffnh, *p_ffnl;
    __nv_bfloat16 *p_qkvTh, *p_qkvTl, *p_woTh, *p_woTl, *p_w1Th, *p_w1Tl, *p_w2Th, *p_w2Tl, *p_outTh, *p_outTl;
    cudaGetSymbolAddress((void**)&p_x, g_x);       cudaGetSymbolAddress((void**)&p_n1, g_n1);
    cudaGetSymbolAddress((void**)&p_qkv, g_qkv);   cudaGetSymbolAddress((void**)&p_att, g_att);
    cudaGetSymbolAddress((void**)&p_n2, g_n2);     cudaGetSymbolAddress((void**)&p_part, g_part);
    cudaGetSymbolAddress((void**)&p_n1h, g_n1h);   cudaGetSymbolAddress((void**)&p_n1l, g_n1l);
    cudaGetSymbolAddress((void**)&p_n2h, g_n2h);   cudaGetSymbolAddress((void**)&p_n2l, g_n2l);
    cudaGetSymbolAddress((void**)&p_valh, g_valh); cudaGetSymbolAddress((void**)&p_vall, g_vall);
    cudaGetSymbolAddress((void**)&p_xh, g_xh);     cudaGetSymbolAddress((void**)&p_xl, g_xl);
    cudaGetSymbolAddress((void**)&p_ffnh, g_ffnh); cudaGetSymbolAddress((void**)&p_ffnl, g_ffnl);
    cudaGetSymbolAddress((void**)&p_qkvTh, g_qkvT_h); cudaGetSymbolAddress((void**)&p_qkvTl, g_qkvT_l);
    cudaGetSymbolAddress((void**)&p_woTh, g_woT_h);   cudaGetSymbolAddress((void**)&p_woTl, g_woT_l);
    cudaGetSymbolAddress((void**)&p_w1Th, g_w1T_h);   cudaGetSymbolAddress((void**)&p_w1Tl, g_w1T_l);
    cudaGetSymbolAddress((void**)&p_w2Th, g_w2T_h);   cudaGetSymbolAddress((void**)&p_w2Tl, g_w2T_l);
    cudaGetSymbolAddress((void**)&p_outTh, g_outT_h); cudaGetSymbolAddress((void**)&p_outTl, g_outT_l);

    dim3 wb(32, 8);
    wconv<<<dim3((3*Dv+31)/32, (Dv+31)/32, Lv), wb>>>(Wqkv, p_qkvTh, p_qkvTl, Dv, 3*Dv);
    wconv<<<dim3((Dv+31)/32, (Dv+31)/32, Lv), wb>>>(Wo, p_woTh, p_woTl, Dv, Dv);
    wconv<<<dim3((HIDv+31)/32, (Dv+31)/32, Lv), wb>>>(W1, p_w1Th, p_w1Tl, Dv, HIDv);
    wconv<<<dim3((Dv+31)/32, (HIDv+31)/32, Lv), wb>>>(W2, p_w2Th, p_w2Tl, HIDv, Dv);
    wconv<<<dim3((Vv+31)/32, (Dv+31)/32, 1), wb>>>(outW, p_outTh, p_outTl, Dv, Vv);

    embed_kernel<<<Mv, 256>>>(vocab, pos, vW, pW);

    for (int l = 0; l < Lv; l++) {
        size_t oq = (size_t)l * 3 * Dv * Dv, oo = (size_t)l * Dv * Dv;
        size_t o1 = (size_t)l * HIDv * Dv,   o2 = (size_t)l * Dv * HIDv;

        ln_kernel<<<Mv, 256>>>(p_x, ln1_s + (long)l*Dv, ln1_b + (long)l*Dv, p_n1, p_n1h, p_n1l);
        // qkv = n1 @ Wqkv + bq -> fp32     [2048 x 2304]
        mma_gemm<0><<<dim3(18, 16, 1), 256, GSMEM>>>(p_n1h, p_n1l, p_qkvTh+oq, p_qkvTl+oq,
            bqkv + (long)l*3*Dv, nullptr, p_qkv, nullptr, nullptr, 3*Dv, Dv, 1);
        attn_kernel<<<dim3(Bv*Hv, Sv/128), 128>>>();
        // att = val @ Wo + bo + x -> fp32  [2048 x 768]
        mma_gemm<1><<<dim3(6, 16, 1), 256, GSMEM>>>(p_valh, p_vall, p_woTh+oo, p_woTl+oo,
            bo + (long)l*Dv, p_x, p_att, nullptr, nullptr, Dv, Dv, 1);
        ln_kernel<<<Mv, 256>>>(p_att, ln2_s + (long)l*Dv, ln2_b + (long)l*Dv, p_n2, p_n2h, p_n2l);
        // ffn = lrelu(n2 @ W1 + b1) -> bf16 hi/lo  [2048 x 9216]
        mma_gemm<2><<<dim3(72, 16, 1), 256, GSMEM>>>(p_n2h, p_n2l, p_w1Th+o1, p_w1Tl+o1,
            b1 + (long)l*HIDv, nullptr, nullptr, p_ffnh, p_ffnl, HIDv, Dv, 1);
        // x = ffn @ W2 + b2 + n2 (split-K=3 + reduce)  [2048 x 768]
        mma_gemm<5><<<dim3(6, 16, 3), 256, GSMEM>>>(p_ffnh, p_ffnl, p_w2Th+o2, p_w2Tl+o2,
            nullptr, nullptr, p_part, nullptr, nullptr, Dv, HIDv, 3);
        reduce_w2<<<Mv*Dv/256, 256>>>(p_part, b2 + (long)l*Dv, p_n2, p_x, p_xh, p_xl);
    }

    // logits = x @ out_W -> fp32   [2048 x 50257]
    mma_gemm<4><<<dim3((Vv + 127)/128, 16, 1), 256, GSMEM>>>(p_xh, p_xl, p_outTh, p_outTl,
        nullptr, nullptr, out, nullptr, nullptr, Vv, Dv, 1);
}

// round 5
// speedup vs baseline: 3.4395x; 1.2578x over previous
#include <cuda_runtime.h>
#include <cuda_bf16.h>
#include <cstdint>
#include <math.h>

#define Bv 2
#define Sv 1024
#define Dv 768
#define Hv 12
#define Lv 12
#define Vv 50257
#define DHv 64
#define HIDv 9216
#define Mv (Bv*Sv)

// ---------------- activation scratch ----------------
__device__ float g_x  [Mv*Dv];
__device__ float g_n1 [Mv*Dv];
__device__ float g_qkv[Mv*3*Dv];
__device__ float g_att[Mv*Dv];
__device__ float g_n2 [Mv*Dv];
__device__ float g_part[3L*Mv*Dv];
__device__ float g_po [2L*Mv*Dv];          // attn partial o (raw)
__device__ float g_pm [2L*Mv*Hv];          // attn partial max
__device__ float g_pl [2L*Mv*Hv];          // attn partial sum
__device__ __nv_bfloat16 g_n1h[Mv*Dv],  g_n1l[Mv*Dv];
__device__ __nv_bfloat16 g_n2h[Mv*Dv],  g_n2l[Mv*Dv];
__device__ __nv_bfloat16 g_valh[Mv*Dv], g_vall[Mv*Dv];
__device__ __nv_bfloat16 g_xh[Mv*Dv],   g_xl[Mv*Dv];
__device__ __nv_bfloat16 g_ffnh[(size_t)Mv*HIDv], g_ffnl[(size_t)Mv*HIDv];
// transposed bf16 hi/lo weight planes ([N,K], K contiguous)
__device__ __nv_bfloat16 g_qkvT_h[(size_t)Lv*3*Dv*Dv], g_qkvT_l[(size_t)Lv*3*Dv*Dv];
__device__ __nv_bfloat16 g_woT_h [(size_t)Lv*Dv*Dv],   g_woT_l [(size_t)Lv*Dv*Dv];
__device__ __nv_bfloat16 g_w1T_h [(size_t)Lv*HIDv*Dv], g_w1T_l [(size_t)Lv*HIDv*Dv];
__device__ __nv_bfloat16 g_w2T_h [(size_t)Lv*Dv*HIDv], g_w2T_l [(size_t)Lv*Dv*HIDv];
__device__ __nv_bfloat16 g_outT_h[(size_t)Vv*Dv],      g_outT_l[(size_t)Vv*Dv];

// ---------------- PTX helpers ----------------
__device__ __forceinline__ uint32_t smem_u32(const void* p) {
    uint32_t a;
    asm("{ .reg .u64 t; cvta.to.shared.u64 t, %1; cvt.u32.u64 %0, t; }" : "=r"(a) : "l"(p));
    return a;
}
__device__ __forceinline__ void cpa16(uint32_t dst, const void* src, bool valid) {
    int sz = valid ? 16 : 0;
    asm volatile("cp.async.cg.shared.global [%0], [%1], 16, %2;"
                 :: "r"(dst), "l"(src), "r"(sz) : "memory");
}
#define CP_COMMIT()  asm volatile("cp.async.commit_group;" ::: "memory")
#define CP_WAIT(n)   asm volatile("cp.async.wait_group %0;" :: "n"(n) : "memory")

__device__ __forceinline__ void ldsm4(uint32_t* r, uint32_t a) {
    asm volatile("ldmatrix.sync.aligned.m8n8.x4.shared.b16 {%0,%1,%2,%3}, [%4];"
        : "=r"(r[0]), "=r"(r[1]), "=r"(r[2]), "=r"(r[3]) : "r"(a));
}
__device__ __forceinline__ void mma16816(float* d, const uint32_t* a, const uint32_t* b) {
    asm volatile("mma.sync.aligned.m16n8k16.row.col.f32.bf16.bf16.f32 "
        "{%0,%1,%2,%3}, {%4,%5,%6,%7}, {%8,%9}, {%0,%1,%2,%3};"
        : "+f"(d[0]), "+f"(d[1]), "+f"(d[2]), "+f"(d[3])
        : "r"(a[0]), "r"(a[1]), "r"(a[2]), "r"(a[3]), "r"(b[0]), "r"(b[1]));
}

// ---------------- bf16x3 tensor-core GEMM ----------------
// C[M,N] = A[M,K] @ B^T (B stored [N,K]); hi/lo planes; tile 256x128, BK=32, 4 stages.
// EPI: 0=+bias->f32  2=+bias,lrelu->bf16 hi/lo  4=plain->f32  5=splitK partial->f32
// smem stage layout: Ah[256x64B] Al Bh[128x64B] Bl; 16B-chunk swizzle c^=((r>>1)&3).
#define STG   49152
#define GSMEM (4*STG)
template<int EPI>
__global__ void __launch_bounds__(256, 1) mma_gemm(
    const __nv_bfloat16* __restrict__ Ah, const __nv_bfloat16* __restrict__ Al,
    const __nv_bfloat16* __restrict__ Bh, const __nv_bfloat16* __restrict__ Bl,
    const float* __restrict__ bias,
    float* __restrict__ C, __nv_bfloat16* __restrict__ Oh, __nv_bfloat16* __restrict__ Ol,
    int N, int K, int ksplit)
{
    extern __shared__ char sm[];
    uint32_t sb = smem_u32(sm);
    int tid = threadIdx.x, wid = tid >> 5, lane = tid & 31;
    int m0 = blockIdx.y * 256, n0 = blockIdx.x * 128;
    int Kper = K / ksplit, kbase = blockIdx.z * Kper, niter = Kper >> 5;

    float acc[4][8][4];
    #pragma unroll
    for (int i = 0; i < 4; i++)
        #pragma unroll
        for (int j = 0; j < 8; j++)
            #pragma unroll
            for (int e = 0; e < 4; e++) acc[i][j][e] = 0.f;

    auto stage_load = [&](int st, int k0) {
        uint32_t base = sb + (uint32_t)st * STG;
        #pragma unroll
        for (int i = tid; i < 1024; i += 256) {
            int r = i >> 2, c = i & 3;
            uint32_t so = base + r * 64 + ((c ^ ((r >> 1) & 3)) << 4);
            size_t ao = (size_t)(m0 + r) * K + k0 + c * 8;
            cpa16(so,         Ah + ao, true);
            cpa16(so + 16384, Al + ao, true);
        }
        #pragma unroll
        for (int i = tid; i < 512; i += 256) {
            int r = i >> 2, c = i & 3;
            uint32_t so = base + 32768 + r * 64 + ((c ^ ((r >> 1) & 3)) << 4);
            bool v = (n0 + r) < N;
            size_t bo = (size_t)(v ? n0 + r : 0) * K + k0 + c * 8;
            cpa16(so,        Bh + bo, v);
            cpa16(so + 8192, Bl + bo, v);
        }
    };

    stage_load(0, kbase); CP_COMMIT();
    stage_load(1, kbase + 32); CP_COMMIT();
    stage_load(2, kbase + 64); CP_COMMIT();

    int wm = (wid & 3) * 64, wn = (wid >> 2) * 64;

    for (int it = 0; it < niter; it++) {
        if (it + 3 < niter) stage_load((it + 3) & 3, kbase + (it + 3) * 32);
        CP_COMMIT();
        CP_WAIT(3);
        __syncthreads();

        uint32_t base = sb + (uint32_t)(it & 3) * STG;
        #pragma unroll
        for (int ks = 0; ks < 2; ks++) {
            uint32_t ah[4][4], al[4][4], bh[4][4], bl[4][4];
            {
                int ar = wm + (lane & 15);
                int c = ks * 2 + (lane >> 4);
                #pragma unroll
                for (int i = 0; i < 4; i++) {
                    int r = ar + i * 16;
                    uint32_t ad = base + r * 64 + ((c ^ ((r >> 1) & 3)) << 4);
                    ldsm4(ah[i], ad);
                    ldsm4(al[i], ad + 16384);
                }
            }
            {
                int br = wn + (lane & 7) + (((lane >> 4) & 1) << 3);
                int c = ks * 2 + ((lane >> 3) & 1);
                #pragma unroll
                for (int j = 0; j < 4; j++) {
                    int r = br + j * 16;
                    uint32_t bd = base + 32768 + r * 64 + ((c ^ ((r >> 1) & 3)) << 4);
                    ldsm4(bh[j], bd);
                    ldsm4(bl[j], bd + 8192);
                }
            }
            #pragma unroll
            for (int i = 0; i < 4; i++)
                #pragma unroll
                for (int jj = 0; jj < 8; jj++) {
                    const uint32_t* bph = &bh[jj >> 1][(jj & 1) * 2];
                    const uint32_t* bpl = &bl[jj >> 1][(jj & 1) * 2];
                    mma16816(acc[i][jj], ah[i], bph);
                    mma16816(acc[i][jj], ah[i], bpl);
                    mma16816(acc[i][jj], al[i], bph);
                }
        }
        __syncthreads();
    }

    #pragma unroll
    for (int i = 0; i < 4; i++) {
        int r0 = m0 + wm + i * 16 + (lane >> 2);
        #pragma unroll
        for (int jj = 0; jj < 8; jj++) {
            int c0 = n0 + wn + jj * 8 + 2 * (lane & 3);
            #pragma unroll
            for (int e = 0; e < 4; e++) {
                int r = r0 + (e >> 1) * 8;
                int c = c0 + (e & 1);
                if (c < N) {
                    float v = acc[i][jj][e];
                    if (EPI == 0 || EPI == 2) v += bias[c];
                    if (EPI == 2) {
                        v = v > 0.f ? v : 0.01f * v;
                        __nv_bfloat16 h = __float2bfloat16(v);
                        Oh[(size_t)r * N + c] = h;
                        Ol[(size_t)r * N + c] = __float2bfloat16(v - __bfloat162float(h));
                    } else if (EPI == 5) {
                        C[(size_t)blockIdx.z * Mv * N + (size_t)r * N + c] = v;
                    } else {
                        C[(size_t)r * N + c] = v;
                    }
                }
            }
        }
    }
}

// ---------------- weight transpose + bf16 hi/lo split ----------------
__global__ void wconv(const float* __restrict__ W, __nv_bfloat16* __restrict__ Th,
                      __nv_bfloat16* __restrict__ Tl, int K, int N) {
    __shared__ float t[32][33];
    size_t zo = (size_t)blockIdx.z * K * N;
    const float* Wp = W + zo;
    __nv_bfloat16* Thp = Th + zo;
    __nv_bfloat16* Tlp = Tl + zo;
    int k0 = blockIdx.y * 32, n0 = blockIdx.x * 32;
    for (int i = threadIdx.y; i < 32; i += 8) {
        int k = k0 + i, n = n0 + threadIdx.x;
        t[i][threadIdx.x] = (k < K && n < N) ? Wp[(size_t)k * N + n] : 0.f;
    }
    __syncthreads();
    for (int i = threadIdx.y; i < 32; i += 8) {
        int n = n0 + i, k = k0 + threadIdx.x;
        if (n < N && k < K) {
            float v = t[threadIdx.x][i];
            __nv_bfloat16 h = __float2bfloat16(v);
            Thp[(size_t)n * K + k] = h;
            Tlp[(size_t)n * K + k] = __float2bfloat16(v - __bfloat162float(h));
        }
    }
}

// ---------------- split-K reduces ----------------
__global__ void reduce_w2(const float* __restrict__ part, const float* __restrict__ b2,
                          const float* __restrict__ n2, float* __restrict__ x,
                          __nv_bfloat16* __restrict__ xh, __nv_bfloat16* __restrict__ xl) {
    int i = blockIdx.x * 256 + threadIdx.x;
    float v = part[i] + part[i + (size_t)Mv * Dv] + part[i + 2ul * Mv * Dv]
            + b2[i % Dv] + n2[i];
    x[i] = v;
    __nv_bfloat16 h = __float2bfloat16(v);
    xh[i] = h; xl[i] = __float2bfloat16(v - __bfloat162float(h));
}
__global__ void reduce_wo(const float* __restrict__ part, const float* __restrict__ bo,
                          const float* __restrict__ x, float* __restrict__ att) {
    int i = blockIdx.x * 256 + threadIdx.x;
    att[i] = part[i] + part[i + (size_t)Mv * Dv] + part[i + 2ul * Mv * Dv]
           + bo[i % Dv] + x[i];
}

// ---------------- embedding ----------------
__global__ void embed_kernel(const int* __restrict__ vocab, const int* __restrict__ pos,
                             const float* __restrict__ vW, const float* __restrict__ pW) {
    int row = blockIdx.x;
    const float* vr = vW + (long)vocab[row] * Dv;
    const float* pr = pW + (long)pos[row] * Dv;
    float* o = g_x + (long)row * Dv;
    for (int d = threadIdx.x; d < Dv; d += blockDim.x) o[d] = vr[d] + pr[d];
}

// ---------------- layernorm (fp32 + hi/lo planes) ----------------
__global__ void __launch_bounds__(256) ln_kernel(const float* __restrict__ in,
        const float* __restrict__ s, const float* __restrict__ b,
        float* __restrict__ out, __nv_bfloat16* __restrict__ oh, __nv_bfloat16* __restrict__ ol) {
    int row = blockIdx.x;
    const float* x = in + (long)row * Dv;
    __shared__ float red[256];
    int tid = threadIdx.x;
    float sum = 0.f;
    for (int d = tid; d < Dv; d += 256) sum += x[d];
    red[tid] = sum; __syncthreads();
    #pragma unroll
    for (int o = 128; o > 0; o >>= 1) { if (tid < o) red[tid] += red[tid + o]; __syncthreads(); }
    float mean = red[0] * (1.0f / Dv);
    __syncthreads();
    float vs = 0.f;
    for (int d = tid; d < Dv; d += 256) { float t = x[d] - mean; vs += t * t; }
    red[tid] = vs; __syncthreads();
    #pragma unroll
    for (int o = 128; o > 0; o >>= 1) { if (tid < o) red[tid] += red[tid + o]; __syncthreads(); }
    float rstd = rsqrtf(red[0] * (1.0f / Dv) + 1e-5f);
    long base = (long)row * Dv;
    for (int d = tid; d < Dv; d += 256) {
        float v = (x[d] - mean) * rstd * s[d] + b[d];
        out[base + d] = v;
        __nv_bfloat16 h = __float2bfloat16(v);
        oh[base + d] = h;
        ol[base + d] = __float2bfloat16(v - __bfloat162float(h));
    }
}

// ---------------- fused attention, key-split in 2 (partials) ----------------
__global__ void __launch_bounds__(128) attn_kernel() {
    int bh = blockIdx.x;
    int b = bh / Hv, h = bh % Hv;
    int qt = blockIdx.y;
    int z  = blockIdx.z;
    int tid = threadIdx.x;
    int qi = qt * 128 + tid;

    const float* qrow = g_qkv + (long)(b * Sv + qi) * (3 * Dv) + h * 3 * DHv;
    float q[DHv];
    #pragma unroll
    for (int d = 0; d < DHv; d++) q[d] = qrow[d];
    float o[DHv];
    #pragma unroll
    for (int d = 0; d < DHv; d++) o[d] = 0.f;
    float mx = -1e30f, l = 0.f;

    __shared__ float Ks[64][DHv];
    __shared__ float Vs[64][DHv];
    int kend = qt * 128 + 128;
    int half = kend >> 1;             // multiple of 64
    int kb = z ? half : 0, ke = z ? kend : half;

    for (int ks0 = kb; ks0 < ke; ks0 += 64) {
        for (int idx = tid; idx < 64 * 16; idx += 128) {
            int j = idx >> 4, dc = (idx & 15) * 4;
            const float* kr = g_qkv + (long)(b * Sv + ks0 + j) * (3 * Dv) + h * 3 * DHv + DHv + dc;
            *(float4*)&Ks[j][dc] = *(const float4*)kr;
            *(float4*)&Vs[j][dc] = *(const float4*)(kr + DHv);
        }
        __syncthreads();
        #pragma unroll 1
        for (int sub = 0; sub < 64; sub += 16) {
            float s[16];
            #pragma unroll
            for (int jj = 0; jj < 16; jj++) {
                float acc = 0.f;
                #pragma unroll
                for (int d = 0; d < DHv; d++) acc = fmaf(q[d], Ks[sub + jj][d], acc);
                int kj = ks0 + sub + jj;
                s[jj] = (kj <= qi) ? acc * 0.125f : -1e5f;
            }
            float cm = s[0];
            #pragma unroll
            for (int jj = 1; jj < 16; jj++) cm = fmaxf(cm, s[jj]);
            float mnew = fmaxf(mx, cm);
            float scale = __expf(mx - mnew);
            l *= scale;
            #pragma unroll
            for (int d = 0; d < DHv; d++) o[d] *= scale;
            #pragma unroll
            for (int jj = 0; jj < 16; jj++) {
                float p = __expf(s[jj] - mnew);
                l += p;
                #pragma unroll
                for (int d = 0; d < DHv; d++) o[d] = fmaf(p, Vs[sub + jj][d], o[d]);
            }
            mx = mnew;
        }
        __syncthreads();
    }
    long row = (long)(b * Sv + qi);
    long ob = (long)z * Mv * Dv + row * Dv + h * DHv;
    #pragma unroll
    for (int d = 0; d < DHv; d++) g_po[ob + d] = o[d];
    g_pm[(long)z * Mv * Hv + row * Hv + h] = mx;
    g_pl[(long)z * Mv * Hv + row * Hv + h] = l;
}

// combine partials -> bf16 hi/lo val planes
__global__ void __launch_bounds__(256) attn_combine() {
    long row = blockIdx.x;
    for (int idx = threadIdx.x; idx < Dv; idx += 256) {
        int h = idx >> 6;
        float m0 = g_pm[row * Hv + h], m1 = g_pm[Mv * Hv + row * Hv + h];
        float l0 = g_pl[row * Hv + h], l1 = g_pl[Mv * Hv + row * Hv + h];
        float M = fmaxf(m0, m1);
        float w0 = __expf(m0 - M), w1 = __expf(m1 - M);
        float den = l0 * w0 + l1 * w1;
        float v = (g_po[row * Dv + idx] * w0 + g_po[(long)Mv * Dv + row * Dv + idx] * w1) / den;
        __nv_bfloat16 hh = __float2bfloat16(v);
        g_valh[row * Dv + idx] = hh;
        g_vall[row * Dv + idx] = __float2bfloat16(v - __bfloat162float(hh));
    }
}

// ---------------- driver ----------------
extern "C" void kernel_launch(void* const* d_in, const int* in_sizes, int n_in,
                              void* d_out, int out_size) {
    (void)in_sizes; (void)n_in; (void)out_size;
    const int*   vocab = (const int*)  d_in[0];
    const int*   pos   = (const int*)  d_in[1];
    const float* vW    = (const float*)d_in[2];
    const float* pW    = (const float*)d_in[3];
    const float* ln1_s = (const float*)d_in[4];
    const float* ln1_b = (const float*)d_in[5];
    const float* Wqkv  = (const float*)d_in[6];
    const float* bqkv  = (const float*)d_in[7];
    const float* Wo    = (const float*)d_in[8];
    const float* bo    = (const float*)d_in[9];
    const float* ln2_s = (const float*)d_in[10];
    const float* ln2_b = (const float*)d_in[11];
    const float* W1    = (const float*)d_in[12];
    const float* b1    = (const float*)d_in[13];
    const float* W2    = (const float*)d_in[14];
    const float* b2    = (const float*)d_in[15];
    const float* outW  = (const float*)d_in[16];
    float* out = (float*)d_out;

    static bool attr_done = false;
    if (!attr_done) {
        cudaFuncSetAttribute(mma_gemm<0>, cudaFuncAttributeMaxDynamicSharedMemorySize, GSMEM);
        cudaFuncSetAttribute(mma_gemm<2>, cudaFuncAttributeMaxDynamicSharedMemorySize, GSMEM);
        cudaFuncSetAttribute(mma_gemm<4>, cudaFuncAttributeMaxDynamicSharedMemorySize, GSMEM);
        cudaFuncSetAttribute(mma_gemm<5>, cudaFuncAttributeMaxDynamicSharedMemorySize, GSMEM);
        attr_done = true;
    }

    float *p_x, *p_n1, *p_qkv, *p_att, *p_n2, *p_part;
    __nv_bfloat16 *p_n1h, *p_n1l, *p_n2h, *p_n2l, *p_xh, *p_xl, *p_ffnh, *p_ffnl, *p_valh, *p_vall;
    __nv_bfloat16 *p_qkvTh, *p_qkvTl, *p_woTh, *p_woTl, *p_w1Th, *p_w1Tl, *p_w2Th, *p_w2Tl, *p_outTh, *p_outTl;
    cudaGetSymbolAddress((void**)&p_x, g_x);       cudaGetSymbolAddress((void**)&p_n1, g_n1);
    cudaGetSymbolAddress((void**)&p_qkv, g_qkv);   cudaGetSymbolAddress((void**)&p_att, g_att);
    cudaGetSymbolAddress((void**)&p_n2, g_n2);     cudaGetSymbolAddress((void**)&p_part, g_part);
    cudaGetSymbolAddress((void**)&p_n1h, g_n1h);   cudaGetSymbolAddress((void**)&p_n1l, g_n1l);
    cudaGetSymbolAddress((void**)&p_n2h, g_n2h);   cudaGetSymbolAddress((void**)&p_n2l, g_n2l);
    cudaGetSymbolAddress((void**)&p_valh, g_valh); cudaGetSymbolAddress((void**)&p_vall, g_vall);
    cudaGetSymbolAddress((void**)&p_xh, g_xh);     cudaGetSymbolAddress((void**)&p_xl, g_xl);
    cudaGetSymbolAddress((void**)&p_ffnh, g_ffnh); cudaGetSymbolAddress((void**)&p_ffnl, g_ffnl);
    cudaGetSymbolAddress((void**)&p_qkvTh, g_qkvT_h); cudaGetSymbolAddress((void**)&p_qkvTl, g_qkvT_l);
    cudaGetSymbolAddress((void**)&p_woTh, g_woT_h);   cudaGetSymbolAddress((void**)&p_woTl, g_woT_l);
    cudaGetSymbolAddress((void**)&p_w1Th, g_w1T_h);   cudaGetSymbolAddress((void**)&p_w1Tl, g_w1T_l);
    cudaGetSymbolAddress((void**)&p_w2Th, g_w2T_h);   cudaGetSymbolAddress((void**)&p_w2Tl, g_w2T_l);
    cudaGetSymbolAddress((void**)&p_outTh, g_outT_h); cudaGetSymbolAddress((void**)&p_outTl, g_outT_l);

    dim3 wb(32, 8);
    wconv<<<dim3((3*Dv+31)/32, (Dv+31)/32, Lv), wb>>>(Wqkv, p_qkvTh, p_qkvTl, Dv, 3*Dv);
    wconv<<<dim3((Dv+31)/32, (Dv+31)/32, Lv), wb>>>(Wo, p_woTh, p_woTl, Dv, Dv);
    wconv<<<dim3((HIDv+31)/32, (Dv+31)/32, Lv), wb>>>(W1, p_w1Th, p_w1Tl, Dv, HIDv);
    wconv<<<dim3((Dv+31)/32, (HIDv+31)/32, Lv), wb>>>(W2, p_w2Th, p_w2Tl, HIDv, Dv);
    wconv<<<dim3((Vv+31)/32, (Dv+31)/32, 1), wb>>>(outW, p_outTh, p_outTl, Dv, Vv);

    embed_kernel<<<Mv, 256>>>(vocab, pos, vW, pW);

    for (int l = 0; l < Lv; l++) {
        size_t oq = (size_t)l * 3 * Dv * Dv, oo = (size_t)l * Dv * Dv;
        size_t o1 = (size_t)l * HIDv * Dv,   o2 = (size_t)l * Dv * HIDv;

        ln_kernel<<<Mv, 256>>>(p_x, ln1_s + (long)l*Dv, ln1_b + (long)l*Dv, p_n1, p_n1h, p_n1l);
        // qkv = n1 @ Wqkv + bq -> fp32   [2048 x 2304]
        mma_gemm<0><<<dim3(18, 8, 1), 256, GSMEM>>>(p_n1h, p_n1l, p_qkvTh+oq, p_qkvTl+oq,
            bqkv + (long)l*3*Dv, p_qkv, nullptr, nullptr, 3*Dv, Dv, 1);
        // attention (key-split x2 + combine)
        attn_kernel<<<dim3(Bv*Hv, Sv/128, 2), 128>>>();
        attn_combine<<<Mv, 256>>>();
        // att = val @ Wo + bo + x   (splitK=3 + reduce)
        mma_gemm<5><<<dim3(6, 8, 3), 256, GSMEM>>>(p_valh, p_vall, p_woTh+oo, p_woTl+oo,
            nullptr, p_part, nullptr, nullptr, Dv, Dv, 3);
        reduce_wo<<<Mv*Dv/256, 256>>>(p_part, bo + (long)l*Dv, p_x, p_att);
        ln_kernel<<<Mv, 256>>>(p_att, ln2_s + (long)l*Dv, ln2_b + (long)l*Dv, p_n2, p_n2h, p_n2l);
        // ffn = lrelu(n2 @ W1 + b1) -> bf16 hi/lo  [2048 x 9216]
        mma_gemm<2><<<dim3(72, 8, 1), 256, GSMEM>>>(p_n2h, p_n2l, p_w1Th+o1, p_w1Tl+o1,
            b1 + (long)l*HIDv, nullptr, p_ffnh, p_ffnl, HIDv, Dv, 1);
        // x = ffn @ W2 + b2 + n2 (splitK=3 + reduce)
        mma_gemm<5><<<dim3(6, 8, 3), 256, GSMEM>>>(p_ffnh, p_ffnl, p_w2Th+o2, p_w2Tl+o2,
            nullptr, p_part, nullptr, nullptr, Dv, HIDv, 3);
        reduce_w2<<<Mv*Dv/256, 256>>>(p_part, b2 + (long)l*Dv, p_n2, p_x, p_xh, p_xl);
    }

    // logits = x @ out_W -> fp32   [2048 x 50257]
    mma_gemm<4><<<dim3((Vv + 127)/128, 8, 1), 256, GSMEM>>>(p_xh, p_xl, p_outTh, p_outTl,
        nullptr, out, nullptr, nullptr, Vv, Dv, 1);
}

// round 6
// speedup vs baseline: 4.0611x; 1.1807x over previous
#include <cuda_runtime.h>
#include <cuda_bf16.h>
#include <cstdint>
#include <math.h>

#define Bv 2
#define Sv 1024
#define Dv 768
#define Hv 12
#define Lv 12
#define Vv 50257
#define DHv 64
#define HIDv 9216
#define Mv (Bv*Sv)

// ---------------- activation scratch ----------------
__device__ float g_x  [Mv*Dv];
__device__ float g_att[Mv*Dv];
__device__ float g_n2 [Mv*Dv];
__device__ float g_part[3L*Mv*Dv];
__device__ __nv_bfloat16 g_n1h[Mv*Dv],  g_n1l[Mv*Dv];
__device__ __nv_bfloat16 g_n2h[Mv*Dv],  g_n2l[Mv*Dv];
__device__ __nv_bfloat16 g_qkvh[Mv*3*Dv], g_qkvl[Mv*3*Dv];
__device__ __nv_bfloat16 g_valh[Mv*Dv], g_vall[Mv*Dv];
__device__ __nv_bfloat16 g_xh[Mv*Dv],   g_xl[Mv*Dv];
__device__ __nv_bfloat16 g_ffnh[(size_t)Mv*HIDv], g_ffnl[(size_t)Mv*HIDv];
// transposed bf16 hi/lo weight planes ([N,K], K contiguous)
__device__ __nv_bfloat16 g_qkvT_h[(size_t)Lv*3*Dv*Dv], g_qkvT_l[(size_t)Lv*3*Dv*Dv];
__device__ __nv_bfloat16 g_woT_h [(size_t)Lv*Dv*Dv],   g_woT_l [(size_t)Lv*Dv*Dv];
__device__ __nv_bfloat16 g_w1T_h [(size_t)Lv*HIDv*Dv], g_w1T_l [(size_t)Lv*HIDv*Dv];
__device__ __nv_bfloat16 g_w2T_h [(size_t)Lv*Dv*HIDv], g_w2T_l [(size_t)Lv*Dv*HIDv];
__device__ __nv_bfloat16 g_outT_h[(size_t)Vv*Dv],      g_outT_l[(size_t)Vv*Dv];

// ---------------- PTX helpers ----------------
__device__ __forceinline__ uint32_t smem_u32(const void* p) {
    uint32_t a;
    asm("{ .reg .u64 t; cvta.to.shared.u64 t, %1; cvt.u32.u64 %0, t; }" : "=r"(a) : "l"(p));
    return a;
}
__device__ __forceinline__ void cpa16(uint32_t dst, const void* src, bool valid) {
    int sz = valid ? 16 : 0;
    asm volatile("cp.async.cg.shared.global [%0], [%1], 16, %2;"
                 :: "r"(dst), "l"(src), "r"(sz) : "memory");
}
#define CP_COMMIT()  asm volatile("cp.async.commit_group;" ::: "memory")
#define CP_WAIT(n)   asm volatile("cp.async.wait_group %0;" :: "n"(n) : "memory")

__device__ __forceinline__ void ldsm4(uint32_t* r, uint32_t a) {
    asm volatile("ldmatrix.sync.aligned.m8n8.x4.shared.b16 {%0,%1,%2,%3}, [%4];"
        : "=r"(r[0]), "=r"(r[1]), "=r"(r[2]), "=r"(r[3]) : "r"(a));
}
__device__ __forceinline__ void ldsm4t(uint32_t* r, uint32_t a) {
    asm volatile("ldmatrix.sync.aligned.m8n8.x4.trans.shared.b16 {%0,%1,%2,%3}, [%4];"
        : "=r"(r[0]), "=r"(r[1]), "=r"(r[2]), "=r"(r[3]) : "r"(a));
}
__device__ __forceinline__ void mma16816(float* d, const uint32_t* a, const uint32_t* b) {
    asm volatile("mma.sync.aligned.m16n8k16.row.col.f32.bf16.bf16.f32 "
        "{%0,%1,%2,%3}, {%4,%5,%6,%7}, {%8,%9}, {%0,%1,%2,%3};"
        : "+f"(d[0]), "+f"(d[1]), "+f"(d[2]), "+f"(d[3])
        : "r"(a[0]), "r"(a[1]), "r"(a[2]), "r"(a[3]), "r"(b[0]), "r"(b[1]));
}
__device__ __forceinline__ uint32_t packbf2(float a, float b) {
    __nv_bfloat162 t = __floats2bfloat162_rn(a, b);
    return *reinterpret_cast<uint32_t*>(&t);
}

// ---------------- bf16x3 tensor-core GEMM ----------------
// C[M,N] = A[M,K] @ B^T (B stored [N,K]); hi/lo planes; tile 256x128, BK=32, 4 stages.
// EPI: 2=+bias,lrelu->bf16 hi/lo  3=+bias->bf16 hi/lo  4=plain->f32  5=splitK partial->f32
#define STG   49152
#define GSMEM (4*STG)
template<int EPI>
__global__ void __launch_bounds__(256, 1) mma_gemm(
    const __nv_bfloat16* __restrict__ Ah, const __nv_bfloat16* __restrict__ Al,
    const __nv_bfloat16* __restrict__ Bh, const __nv_bfloat16* __restrict__ Bl,
    const float* __restrict__ bias,
    float* __restrict__ C, __nv_bfloat16* __restrict__ Oh, __nv_bfloat16* __restrict__ Ol,
    int N, int K, int ksplit)
{
    extern __shared__ char sm[];
    uint32_t sb = smem_u32(sm);
    int tid = threadIdx.x, wid = tid >> 5, lane = tid & 31;
    int m0 = blockIdx.y * 256, n0 = blockIdx.x * 128;
    int Kper = K / ksplit, kbase = blockIdx.z * Kper, niter = Kper >> 5;

    float acc[4][8][4];
    #pragma unroll
    for (int i = 0; i < 4; i++)
        #pragma unroll
        for (int j = 0; j < 8; j++)
            #pragma unroll
            for (int e = 0; e < 4; e++) acc[i][j][e] = 0.f;

    auto stage_load = [&](int st, int k0) {
        uint32_t base = sb + (uint32_t)st * STG;
        #pragma unroll
        for (int i = tid; i < 1024; i += 256) {
            int r = i >> 2, c = i & 3;
            uint32_t so = base + r * 64 + ((c ^ ((r >> 1) & 3)) << 4);
            size_t ao = (size_t)(m0 + r) * K + k0 + c * 8;
            cpa16(so,         Ah + ao, true);
            cpa16(so + 16384, Al + ao, true);
        }
        #pragma unroll
        for (int i = tid; i < 512; i += 256) {
            int r = i >> 2, c = i & 3;
            uint32_t so = base + 32768 + r * 64 + ((c ^ ((r >> 1) & 3)) << 4);
            bool v = (n0 + r) < N;
            size_t bo = (size_t)(v ? n0 + r : 0) * K + k0 + c * 8;
            cpa16(so,        Bh + bo, v);
            cpa16(so + 8192, Bl + bo, v);
        }
    };

    stage_load(0, kbase); CP_COMMIT();
    stage_load(1, kbase + 32); CP_COMMIT();
    stage_load(2, kbase + 64); CP_COMMIT();

    int wm = (wid & 3) * 64, wn = (wid >> 2) * 64;

    for (int it = 0; it < niter; it++) {
        if (it + 3 < niter) stage_load((it + 3) & 3, kbase + (it + 3) * 32);
        CP_COMMIT();
        CP_WAIT(3);
        __syncthreads();

        uint32_t base = sb + (uint32_t)(it & 3) * STG;
        #pragma unroll
        for (int ks = 0; ks < 2; ks++) {
            uint32_t ah[4][4], al[4][4], bh[4][4], bl[4][4];
            {
                int ar = wm + (lane & 15);
                int c = ks * 2 + (lane >> 4);
                #pragma unroll
                for (int i = 0; i < 4; i++) {
                    int r = ar + i * 16;
                    uint32_t ad = base + r * 64 + ((c ^ ((r >> 1) & 3)) << 4);
                    ldsm4(ah[i], ad);
                    ldsm4(al[i], ad + 16384);
                }
            }
            {
                int br = wn + (lane & 7) + (((lane >> 4) & 1) << 3);
                int c = ks * 2 + ((lane >> 3) & 1);
                #pragma unroll
                for (int j = 0; j < 4; j++) {
                    int r = br + j * 16;
                    uint32_t bd = base + 32768 + r * 64 + ((c ^ ((r >> 1) & 3)) << 4);
                    ldsm4(bh[j], bd);
                    ldsm4(bl[j], bd + 8192);
                }
            }
            #pragma unroll
            for (int i = 0; i < 4; i++)
                #pragma unroll
                for (int jj = 0; jj < 8; jj++) {
                    const uint32_t* bph = &bh[jj >> 1][(jj & 1) * 2];
                    const uint32_t* bpl = &bl[jj >> 1][(jj & 1) * 2];
                    mma16816(acc[i][jj], ah[i], bph);
                    mma16816(acc[i][jj], ah[i], bpl);
                    mma16816(acc[i][jj], al[i], bph);
                }
        }
        __syncthreads();
    }

    #pragma unroll
    for (int i = 0; i < 4; i++) {
        int r0 = m0 + wm + i * 16 + (lane >> 2);
        #pragma unroll
        for (int jj = 0; jj < 8; jj++) {
            int c0 = n0 + wn + jj * 8 + 2 * (lane & 3);
            #pragma unroll
            for (int e = 0; e < 4; e++) {
                int r = r0 + (e >> 1) * 8;
                int c = c0 + (e & 1);
                if (c < N) {
                    float v = acc[i][jj][e];
                    if (EPI == 2 || EPI == 3) v += bias[c];
                    if (EPI == 2) v = v > 0.f ? v : 0.01f * v;
                    if (EPI == 2 || EPI == 3) {
                        __nv_bfloat16 h = __float2bfloat16(v);
                        Oh[(size_t)r * N + c] = h;
                        Ol[(size_t)r * N + c] = __float2bfloat16(v - __bfloat162float(h));
                    } else if (EPI == 5) {
                        C[(size_t)blockIdx.z * Mv * N + (size_t)r * N + c] = v;
                    } else {
                        C[(size_t)r * N + c] = v;
                    }
                }
            }
        }
    }
}

// ---------------- weight transpose + bf16 hi/lo split ----------------
__global__ void wconv(const float* __restrict__ W, __nv_bfloat16* __restrict__ Th,
                      __nv_bfloat16* __restrict__ Tl, int K, int N) {
    __shared__ float t[32][33];
    size_t zo = (size_t)blockIdx.z * K * N;
    const float* Wp = W + zo;
    __nv_bfloat16* Thp = Th + zo;
    __nv_bfloat16* Tlp = Tl + zo;
    int k0 = blockIdx.y * 32, n0 = blockIdx.x * 32;
    for (int i = threadIdx.y; i < 32; i += 8) {
        int k = k0 + i, n = n0 + threadIdx.x;
        t[i][threadIdx.x] = (k < K && n < N) ? Wp[(size_t)k * N + n] : 0.f;
    }
    __syncthreads();
    for (int i = threadIdx.y; i < 32; i += 8) {
        int n = n0 + i, k = k0 + threadIdx.x;
        if (n < N && k < K) {
            float v = t[threadIdx.x][i];
            __nv_bfloat16 h = __float2bfloat16(v);
            Thp[(size_t)n * K + k] = h;
            Tlp[(size_t)n * K + k] = __float2bfloat16(v - __bfloat162float(h));
        }
    }
}

// ---------------- split-K reduces ----------------
__global__ void reduce_w2(const float* __restrict__ part, const float* __restrict__ b2,
                          const float* __restrict__ n2, float* __restrict__ x,
                          __nv_bfloat16* __restrict__ xh, __nv_bfloat16* __restrict__ xl) {
    int i = blockIdx.x * 256 + threadIdx.x;
    float v = part[i] + part[i + (size_t)Mv * Dv] + part[i + 2ul * Mv * Dv]
            + b2[i % Dv] + n2[i];
    x[i] = v;
    __nv_bfloat16 h = __float2bfloat16(v);
    xh[i] = h; xl[i] = __float2bfloat16(v - __bfloat162float(h));
}
__global__ void reduce_wo(const float* __restrict__ part, const float* __restrict__ bo,
                          const float* __restrict__ x, float* __restrict__ att) {
    int i = blockIdx.x * 256 + threadIdx.x;
    att[i] = part[i] + part[i + (size_t)Mv * Dv] + part[i + 2ul * Mv * Dv]
           + bo[i % Dv] + x[i];
}

// ---------------- embedding ----------------
__global__ void embed_kernel(const int* __restrict__ vocab, const int* __restrict__ pos,
                             const float* __restrict__ vW, const float* __restrict__ pW) {
    int row = blockIdx.x;
    const float* vr = vW + (long)vocab[row] * Dv;
    const float* pr = pW + (long)pos[row] * Dv;
    float* o = g_x + (long)row * Dv;
    for (int d = threadIdx.x; d < Dv; d += blockDim.x) o[d] = vr[d] + pr[d];
}

// ---------------- layernorm (optional fp32 out + hi/lo planes) ----------------
__global__ void __launch_bounds__(256) ln_kernel(const float* __restrict__ in,
        const float* __restrict__ s, const float* __restrict__ b,
        float* __restrict__ out, __nv_bfloat16* __restrict__ oh, __nv_bfloat16* __restrict__ ol) {
    int row = blockIdx.x;
    const float* x = in + (long)row * Dv;
    __shared__ float red[256];
    int tid = threadIdx.x;
    float sum = 0.f;
    for (int d = tid; d < Dv; d += 256) sum += x[d];
    red[tid] = sum; __syncthreads();
    #pragma unroll
    for (int o = 128; o > 0; o >>= 1) { if (tid < o) red[tid] += red[tid + o]; __syncthreads(); }
    float mean = red[0] * (1.0f / Dv);
    __syncthreads();
    float vs = 0.f;
    for (int d = tid; d < Dv; d += 256) { float t = x[d] - mean; vs += t * t; }
    red[tid] = vs; __syncthreads();
    #pragma unroll
    for (int o = 128; o > 0; o >>= 1) { if (tid < o) red[tid] += red[tid + o]; __syncthreads(); }
    float rstd = rsqrtf(red[0] * (1.0f / Dv) + 1e-5f);
    long base = (long)row * Dv;
    for (int d = tid; d < Dv; d += 256) {
        float v = (x[d] - mean) * rstd * s[d] + b[d];
        if (out) out[base + d] = v;
        __nv_bfloat16 h = __float2bfloat16(v);
        oh[base + d] = h;
        ol[base + d] = __float2bfloat16(v - __bfloat162float(h));
    }
}

// ---------------- tensor-core flash attention ----------------
// grid (Bv*Hv, 8), 128 threads (4 warps). Block y handles q-tiles y and 15-y
// (64 queries each). bf16 hi/lo x3 MMAs for both QK^T and PV.
__global__ void __launch_bounds__(128) attn_tc() {
    __shared__ char smQ[16384];
    __shared__ char smK[16384];
    __shared__ char smV[16384];
    int bh = blockIdx.x, b = bh / Hv, h = bh % Hv;
    int tid = threadIdx.x, w = tid >> 5, lane = tid & 31;
    uint32_t qsb = smem_u32(smQ), ksb = smem_u32(smK), vsb = smem_u32(smV);

    #pragma unroll 1
    for (int hf = 0; hf < 2; hf++) {
        int qt = hf ? (15 - (int)blockIdx.y) : (int)blockIdx.y;
        int q0 = qt * 64;
        __syncthreads();
        // Q tile -> smem hi/lo (64 rows x 64 dh)
        for (int i = tid; i < 512; i += 128) {
            int r = i >> 3, c = i & 7;
            uint32_t off = r * 128 + ((c ^ (r & 7)) << 4);
            size_t src = (size_t)(b * Sv + q0 + r) * (3 * Dv) + h * 3 * DHv + c * 8;
            cpa16(qsb + off,        g_qkvh + src, true);
            cpa16(qsb + 8192 + off, g_qkvl + src, true);
        }
        CP_COMMIT(); CP_WAIT(0); __syncthreads();
        uint32_t qh[4][4], ql[4][4];
        {
            int r = w * 16 + (lane & 15);
            #pragma unroll
            for (int kt = 0; kt < 4; kt++) {
                uint32_t off = r * 128 + (((kt * 2 + (lane >> 4)) ^ (r & 7)) << 4);
                ldsm4(qh[kt], qsb + off);
                ldsm4(ql[kt], qsb + 8192 + off);
            }
        }
        float o_acc[8][4];
        #pragma unroll
        for (int jd = 0; jd < 8; jd++)
            #pragma unroll
            for (int e = 0; e < 4; e++) o_acc[jd][e] = 0.f;
        float m_lo = -1e30f, m_hi = -1e30f, l_lo = 0.f, l_hi = 0.f;
        int qi_lo = q0 + w * 16 + (lane >> 2);
        int nch = qt + 1;

        #pragma unroll 1
        for (int ch = 0; ch < nch; ch++) {
            int ks0 = ch * 64;
            __syncthreads();
            for (int i = tid; i < 512; i += 128) {
                int r = i >> 3, c = i & 7;
                uint32_t off = r * 128 + ((c ^ (r & 7)) << 4);
                size_t base = (size_t)(b * Sv + ks0 + r) * (3 * Dv) + h * 3 * DHv;
                cpa16(ksb + off,        g_qkvh + base + DHv + c * 8, true);
                cpa16(ksb + 8192 + off, g_qkvl + base + DHv + c * 8, true);
                cpa16(vsb + off,        g_qkvh + base + 2 * DHv + c * 8, true);
                cpa16(vsb + 8192 + off, g_qkvl + base + 2 * DHv + c * 8, true);
            }
            CP_COMMIT(); CP_WAIT(0); __syncthreads();

            // S = Q K^T  (16 q-rows per warp x 64 keys)
            float s_acc[8][4];
            #pragma unroll
            for (int jn = 0; jn < 8; jn++)
                #pragma unroll
                for (int e = 0; e < 4; e++) s_acc[jn][e] = 0.f;
            #pragma unroll
            for (int kt = 0; kt < 4; kt++) {
                uint32_t kh_[4][4], kl_[4][4];
                int br = (lane & 7) + (((lane >> 4) & 1) << 3);
                int cc = kt * 2 + ((lane >> 3) & 1);
                #pragma unroll
                for (int j = 0; j < 4; j++) {
                    int r = br + j * 16;
                    uint32_t off = r * 128 + ((cc ^ (r & 7)) << 4);
                    ldsm4(kh_[j], ksb + off);
                    ldsm4(kl_[j], ksb + 8192 + off);
                }
                #pragma unroll
                for (int jn = 0; jn < 8; jn++) {
                    const uint32_t* bph = &kh_[jn >> 1][(jn & 1) * 2];
                    const uint32_t* bpl = &kl_[jn >> 1][(jn & 1) * 2];
                    mma16816(s_acc[jn], qh[kt], bph);
                    mma16816(s_acc[jn], qh[kt], bpl);
                    mma16816(s_acc[jn], ql[kt], bph);
                }
            }

            // scale + mask + online softmax
            bool mk = (ch == nch - 1);
            float cm_lo = -1e30f, cm_hi = -1e30f;
            #pragma unroll
            for (int jn = 0; jn < 8; jn++)
                #pragma unroll
                for (int e = 0; e < 4; e++) {
                    int n = ks0 + jn * 8 + ((lane & 3) << 1) + (e & 1);
                    float s = s_acc[jn][e] * 0.125f;
                    if (mk && n > qi_lo + (e >> 1) * 8) s = -1e5f;
                    s_acc[jn][e] = s;
                    if (e < 2) cm_lo = fmaxf(cm_lo, s); else cm_hi = fmaxf(cm_hi, s);
                }
            cm_lo = fmaxf(cm_lo, __shfl_xor_sync(0xffffffffu, cm_lo, 1));
            cm_lo = fmaxf(cm_lo, __shfl_xor_sync(0xffffffffu, cm_lo, 2));
            cm_hi = fmaxf(cm_hi, __shfl_xor_sync(0xffffffffu, cm_hi, 1));
            cm_hi = fmaxf(cm_hi, __shfl_xor_sync(0xffffffffu, cm_hi, 2));
            float mn_lo = fmaxf(m_lo, cm_lo), mn_hi = fmaxf(m_hi, cm_hi);
            float sc_lo = __expf(m_lo - mn_lo), sc_hi = __expf(m_hi - mn_hi);
            m_lo = mn_lo; m_hi = mn_hi;
            l_lo *= sc_lo; l_hi *= sc_hi;
            #pragma unroll
            for (int jd = 0; jd < 8; jd++) {
                o_acc[jd][0] *= sc_lo; o_acc[jd][1] *= sc_lo;
                o_acc[jd][2] *= sc_hi; o_acc[jd][3] *= sc_hi;
            }

            // P fragments (hi/lo) directly from S accumulators
            uint32_t ph[4][4], pl[4][4];
            #pragma unroll
            for (int k2 = 0; k2 < 4; k2++) {
                #pragma unroll
                for (int jj = 0; jj < 2; jj++) {
                    int j = k2 * 2 + jj;
                    float p0 = __expf(s_acc[j][0] - mn_lo);
                    float p1 = __expf(s_acc[j][1] - mn_lo);
                    float p2 = __expf(s_acc[j][2] - mn_hi);
                    float p3 = __expf(s_acc[j][3] - mn_hi);
                    l_lo += p0 + p1; l_hi += p2 + p3;
                    uint32_t hA = packbf2(p0, p1), hB = packbf2(p2, p3);
                    ph[k2][jj * 2]     = hA;
                    ph[k2][jj * 2 + 1] = hB;
                    __nv_bfloat162 tA = *(__nv_bfloat162*)&hA;
                    __nv_bfloat162 tB = *(__nv_bfloat162*)&hB;
                    pl[k2][jj * 2]     = packbf2(p0 - __bfloat162float(tA.x),
                                                 p1 - __bfloat162float(tA.y));
                    pl[k2][jj * 2 + 1] = packbf2(p2 - __bfloat162float(tB.x),
                                                 p3 - __bfloat162float(tB.y));
                }
            }

            // O += P V
            #pragma unroll
            for (int k2 = 0; k2 < 4; k2++) {
                #pragma unroll
                for (int jp = 0; jp < 4; jp++) {
                    uint32_t vh_[4], vl_[4];
                    int g = lane >> 3, t = lane & 7;
                    int r = k2 * 16 + ((g & 1) << 3) + t;
                    int c = jp * 2 + (g >> 1);
                    uint32_t off = r * 128 + ((c ^ (r & 7)) << 4);
                    ldsm4t(vh_, vsb + off);
                    ldsm4t(vl_, vsb + 8192 + off);
                    mma16816(o_acc[jp * 2],     ph[k2], &vh_[0]);
                    mma16816(o_acc[jp * 2],     ph[k2], &vl_[0]);
                    mma16816(o_acc[jp * 2],     pl[k2], &vh_[0]);
                    mma16816(o_acc[jp * 2 + 1], ph[k2], &vh_[2]);
                    mma16816(o_acc[jp * 2 + 1], ph[k2], &vl_[2]);
                    mma16816(o_acc[jp * 2 + 1], pl[k2], &vh_[2]);
                }
            }
        }

        // finalize rows
        l_lo += __shfl_xor_sync(0xffffffffu, l_lo, 1);
        l_lo += __shfl_xor_sync(0xffffffffu, l_lo, 2);
        l_hi += __shfl_xor_sync(0xffffffffu, l_hi, 1);
        l_hi += __shfl_xor_sync(0xffffffffu, l_hi, 2);
        float inv_lo = 1.f / l_lo, inv_hi = 1.f / l_hi;
        long row_lo = (long)(b * Sv + qi_lo);
        long row_hi = row_lo + 8;
        #pragma unroll
        for (int jd = 0; jd < 8; jd++) {
            int col = h * DHv + jd * 8 + ((lane & 3) << 1);
            float v0 = o_acc[jd][0] * inv_lo, v1 = o_acc[jd][1] * inv_lo;
            float v2 = o_acc[jd][2] * inv_hi, v3 = o_acc[jd][3] * inv_hi;
            uint32_t h0 = packbf2(v0, v1);
            __nv_bfloat162 t0 = *(__nv_bfloat162*)&h0;
            uint32_t z0 = packbf2(v0 - __bfloat162float(t0.x), v1 - __bfloat162float(t0.y));
            *(uint32_t*)&g_valh[row_lo * Dv + col] = h0;
            *(uint32_t*)&g_vall[row_lo * Dv + col] = z0;
            uint32_t h1 = packbf2(v2, v3);
            __nv_bfloat162 t1 = *(__nv_bfloat162*)&h1;
            uint32_t z1 = packbf2(v2 - __bfloat162float(t1.x), v3 - __bfloat162float(t1.y));
            *(uint32_t*)&g_valh[row_hi * Dv + col] = h1;
            *(uint32_t*)&g_vall[row_hi * Dv + col] = z1;
        }
    }
}

// ---------------- driver ----------------
extern "C" void kernel_launch(void* const* d_in, const int* in_sizes, int n_in,
                              void* d_out, int out_size) {
    (void)in_sizes; (void)n_in; (void)out_size;
    const int*   vocab = (const int*)  d_in[0];
    const int*   pos   = (const int*)  d_in[1];
    const float* vW    = (const float*)d_in[2];
    const float* pW    = (const float*)d_in[3];
    const float* ln1_s = (const float*)d_in[4];
    const float* ln1_b = (const float*)d_in[5];
    const float* Wqkv  = (const float*)d_in[6];
    const float* bqkv  = (const float*)d_in[7];
    const float* Wo    = (const float*)d_in[8];
    const float* bo    = (const float*)d_in[9];
    const float* ln2_s = (const float*)d_in[10];
    const float* ln2_b = (const float*)d_in[11];
    const float* W1    = (const float*)d_in[12];
    const float* b1    = (const float*)d_in[13];
    const float* W2    = (const float*)d_in[14];
    const float* b2    = (const float*)d_in[15];
    const float* outW  = (const float*)d_in[16];
    float* out = (float*)d_out;

    static bool attr_done = false;
    if (!attr_done) {
        cudaFuncSetAttribute(mma_gemm<2>, cudaFuncAttributeMaxDynamicSharedMemorySize, GSMEM);
        cudaFuncSetAttribute(mma_gemm<3>, cudaFuncAttributeMaxDynamicSharedMemorySize, GSMEM);
        cudaFuncSetAttribute(mma_gemm<4>, cudaFuncAttributeMaxDynamicSharedMemorySize, GSMEM);
        cudaFuncSetAttribute(mma_gemm<5>, cudaFuncAttributeMaxDynamicSharedMemorySize, GSMEM);
        attr_done = true;
    }

    float *p_x, *p_att, *p_n2, *p_part;
    __nv_bfloat16 *p_n1h, *p_n1l, *p_n2h, *p_n2l, *p_qkvh, *p_qkvl, *p_valh, *p_vall,
                  *p_xh, *p_xl, *p_ffnh, *p_ffnl;
    __nv_bfloat16 *p_qkvTh, *p_qkvTl, *p_woTh, *p_woTl, *p_w1Th, *p_w1Tl, *p_w2Th, *p_w2Tl,
                  *p_outTh, *p_outTl;
    cudaGetSymbolAddress((void**)&p_x, g_x);       cudaGetSymbolAddress((void**)&p_att, g_att);
    cudaGetSymbolAddress((void**)&p_n2, g_n2);     cudaGetSymbolAddress((void**)&p_part, g_part);
    cudaGetSymbolAddress((void**)&p_n1h, g_n1h);   cudaGetSymbolAddress((void**)&p_n1l, g_n1l);
    cudaGetSymbolAddress((void**)&p_n2h, g_n2h);   cudaGetSymbolAddress((void**)&p_n2l, g_n2l);
    cudaGetSymbolAddress((void**)&p_qkvh, g_qkvh); cudaGetSymbolAddress((void**)&p_qkvl, g_qkvl);
    cudaGetSymbolAddress((void**)&p_valh, g_valh); cudaGetSymbolAddress((void**)&p_vall, g_vall);
    cudaGetSymbolAddress((void**)&p_xh, g_xh);     cudaGetSymbolAddress((void**)&p_xl, g_xl);
    cudaGetSymbolAddress((void**)&p_ffnh, g_ffnh); cudaGetSymbolAddress((void**)&p_ffnl, g_ffnl);
    cudaGetSymbolAddress((void**)&p_qkvTh, g_qkvT_h); cudaGetSymbolAddress((void**)&p_qkvTl, g_qkvT_l);
    cudaGetSymbolAddress((void**)&p_woTh, g_woT_h);   cudaGetSymbolAddress((void**)&p_woTl, g_woT_l);
    cudaGetSymbolAddress((void**)&p_w1Th, g_w1T_h);   cudaGetSymbolAddress((void**)&p_w1Tl, g_w1T_l);
    cudaGetSymbolAddress((void**)&p_w2Th, g_w2T_h);   cudaGetSymbolAddress((void**)&p_w2Tl, g_w2T_l);
    cudaGetSymbolAddress((void**)&p_outTh, g_outT_h); cudaGetSymbolAddress((void**)&p_outTl, g_outT_l);

    dim3 wb(32, 8);
    wconv<<<dim3((3*Dv+31)/32, (Dv+31)/32, Lv), wb>>>(Wqkv, p_qkvTh, p_qkvTl, Dv, 3*Dv);
    wconv<<<dim3((Dv+31)/32, (Dv+31)/32, Lv), wb>>>(Wo, p_woTh, p_woTl, Dv, Dv);
    wconv<<<dim3((HIDv+31)/32, (Dv+31)/32, Lv), wb>>>(W1, p_w1Th, p_w1Tl, Dv, HIDv);
    wconv<<<dim3((Dv+31)/32, (HIDv+31)/32, Lv), wb>>>(W2, p_w2Th, p_w2Tl, HIDv, Dv);
    wconv<<<dim3((Vv+31)/32, (Dv+31)/32, 1), wb>>>(outW, p_outTh, p_outTl, Dv, Vv);

    embed_kernel<<<Mv, 256>>>(vocab, pos, vW, pW);

    for (int l = 0; l < Lv; l++) {
        size_t oq = (size_t)l * 3 * Dv * Dv, oo = (size_t)l * Dv * Dv;
        size_t o1 = (size_t)l * HIDv * Dv,   o2 = (size_t)l * Dv * HIDv;

        ln_kernel<<<Mv, 256>>>(p_x, ln1_s + (long)l*Dv, ln1_b + (long)l*Dv,
                               nullptr, p_n1h, p_n1l);
        // qkv = n1 @ Wqkv + bq -> bf16 hi/lo planes  [2048 x 2304]
        mma_gemm<3><<<dim3(18, 8, 1), 256, GSMEM>>>(p_n1h, p_n1l, p_qkvTh+oq, p_qkvTl+oq,
            bqkv + (long)l*3*Dv, nullptr, p_qkvh, p_qkvl, 3*Dv, Dv, 1);
        // tensor-core flash attention -> val hi/lo
        attn_tc<<<dim3(Bv*Hv, 8), 128>>>();
        // att = val @ Wo + bo + x   (splitK=3 + reduce)
        mma_gemm<5><<<dim3(6, 8, 3), 256, GSMEM>>>(p_valh, p_vall, p_woTh+oo, p_woTl+oo,
            nullptr, p_part, nullptr, nullptr, Dv, Dv, 3);
        reduce_wo<<<Mv*Dv/256, 256>>>(p_part, bo + (long)l*Dv, p_x, p_att);
        ln_kernel<<<Mv, 256>>>(p_att, ln2_s + (long)l*Dv, ln2_b + (long)l*Dv,
                               p_n2, p_n2h, p_n2l);
        // ffn = lrelu(n2 @ W1 + b1) -> bf16 hi/lo  [2048 x 9216]
        mma_gemm<2><<<dim3(72, 8, 1), 256, GSMEM>>>(p_n2h, p_n2l, p_w1Th+o1, p_w1Tl+o1,
            b1 + (long)l*HIDv, nullptr, p_ffnh, p_ffnl, HIDv, Dv, 1);
        // x = ffn @ W2 + b2 + n2 (splitK=3 + reduce)
        mma_gemm<5><<<dim3(6, 8, 3), 256, GSMEM>>>(p_ffnh, p_ffnl, p_w2Th+o2, p_w2Tl+o2,
            nullptr, p_part, nullptr, nullptr, Dv, HIDv, 3);
        reduce_w2<<<Mv*Dv/256, 256>>>(p_part, b2 + (long)l*Dv, p_n2, p_x, p_xh, p_xl);
    }

    // logits = x @ out_W -> fp32   [2048 x 50257]
    mma_gemm<4><<<dim3((Vv + 127)/128, 8, 1), 256, GSMEM>>>(p_xh, p_xl, p_outTh, p_outTl,
        nullptr, out, nullptr, nullptr, Vv, Dv, 1);
}